// round 1
// baseline (speedup 1.0000x reference)
#include <cuda_runtime.h>
#include <math.h>

#define SEQ     4096
#define BATCH   2
#define EMB     1024
#define NHEADS  16
#define HDIM    64
#define WINSZ   256
#define NCHUNK  (SEQ / WINSZ)      // 16
#define M_TOTAL (BATCH * SEQ)      // 8192

// Scratch (allocation-free rule: __device__ globals)
__device__ float g_q[(size_t)M_TOTAL * EMB];
__device__ float g_k[(size_t)M_TOTAL * EMB];
__device__ float g_v[(size_t)M_TOTAL * EMB];
__device__ float g_ctx[(size_t)M_TOTAL * EMB];

// ---------------------------------------------------------------------------
// SGEMM: C[M,N] = A[M,K] @ B[N,K]^T + bias[N]
// 128x128 block, BK=16, 256 threads, 8x8 per thread.
// ---------------------------------------------------------------------------
__global__ __launch_bounds__(256, 2) void sgemm_bias_kernel(
    const float* __restrict__ A,
    const float* __restrict__ B,      // [N, K] row-major (weight)
    const float* __restrict__ bias,   // [N]
    float* __restrict__ C,
    int M, int N, int K)
{
    __shared__ float As[16][128];
    __shared__ float Bs[16][128];

    const int tid = threadIdx.x;
    const int m0 = blockIdx.y * 128;
    const int n0 = blockIdx.x * 128;

    const int lr = tid >> 1;          // 0..127 : tile row
    const int lc = (tid & 1) << 3;    // 0 or 8 : k offset
    const int tm = (tid & 15) << 3;   // thread m base
    const int tn = (tid >> 4) << 3;   // thread n base

    const float* Aptr = A + (size_t)(m0 + lr) * K + lc;
    const float* Bptr = B + (size_t)(n0 + lr) * K + lc;

    float acc[8][8];
#pragma unroll
    for (int i = 0; i < 8; i++)
#pragma unroll
        for (int j = 0; j < 8; j++) acc[i][j] = 0.0f;

    for (int k0 = 0; k0 < K; k0 += 16) {
        float4 a0 = *(const float4*)(Aptr + k0);
        float4 a1 = *(const float4*)(Aptr + k0 + 4);
        float4 b0 = *(const float4*)(Bptr + k0);
        float4 b1 = *(const float4*)(Bptr + k0 + 4);

        __syncthreads();   // previous iteration's reads complete
        As[lc + 0][lr] = a0.x; As[lc + 1][lr] = a0.y;
        As[lc + 2][lr] = a0.z; As[lc + 3][lr] = a0.w;
        As[lc + 4][lr] = a1.x; As[lc + 5][lr] = a1.y;
        As[lc + 6][lr] = a1.z; As[lc + 7][lr] = a1.w;
        Bs[lc + 0][lr] = b0.x; Bs[lc + 1][lr] = b0.y;
        Bs[lc + 2][lr] = b0.z; Bs[lc + 3][lr] = b0.w;
        Bs[lc + 4][lr] = b1.x; Bs[lc + 5][lr] = b1.y;
        Bs[lc + 6][lr] = b1.z; Bs[lc + 7][lr] = b1.w;
        __syncthreads();

#pragma unroll
        for (int kk = 0; kk < 16; kk++) {
            float ar[8], br[8];
            *(float4*)&ar[0] = *(const float4*)&As[kk][tm];
            *(float4*)&ar[4] = *(const float4*)&As[kk][tm + 4];
            *(float4*)&br[0] = *(const float4*)&Bs[kk][tn];
            *(float4*)&br[4] = *(const float4*)&Bs[kk][tn + 4];
#pragma unroll
            for (int i = 0; i < 8; i++)
#pragma unroll
                for (int j = 0; j < 8; j++)
                    acc[i][j] = fmaf(ar[i], br[j], acc[i][j]);
        }
    }

#pragma unroll
    for (int i = 0; i < 8; i++) {
        size_t row = (size_t)(m0 + tm + i) * N + n0 + tn;
#pragma unroll
        for (int j = 0; j < 8; j++)
            C[row + j] = acc[i][j] + bias[n0 + tn + j];
    }
}

// ---------------------------------------------------------------------------
// RoPE (reference quirk: angle = head_index * inv[t % 32]; interleaved x2).
// One thread per even/odd pair. In-place. q additionally scaled by 1/8.
// ---------------------------------------------------------------------------
__global__ void rope_kernel(float* __restrict__ x, float scale, int total_pairs)
{
    int pid = blockIdx.x * blockDim.x + threadIdx.x;
    if (pid >= total_pairs) return;
    int base = pid << 1;
    int col = base & (EMB - 1);
    int hh = col >> 6;          // head index
    int t  = col & 63;          // even dim index within head
    int j0 = t & 31;
    int j1 = (t + 1) & 31;
    // inv[j] = 10000^(-2j/64) = exp(-ln(10000)*j/32)
    const float kln = 0.28782313662425572f;   // ln(10000)/32
    float a0 = (float)hh * __expf(-kln * (float)j0);
    float a1 = (float)hh * __expf(-kln * (float)j1);
    float s0, c0, s1, c1;
    sincosf(a0, &s0, &c0);
    sincosf(a1, &s1, &c1);
    float x0 = x[base], x1 = x[base + 1];
    x[base]     = (x0 * c0 - x1 * s0) * scale;
    x[base + 1] = (x1 * c1 + x0 * s1) * scale;
}

// ---------------------------------------------------------------------------
// Windowed attention. Block = (chunk, head, batch). 256 threads = 256 queries.
// K/V band (768 keys) streamed in 3 tiles of 256 through dynamic smem.
// Online softmax, acc[64] in registers.
// ---------------------------------------------------------------------------
__global__ __launch_bounds__(256, 1) void attn_kernel(
    const float* __restrict__ q,
    const float* __restrict__ k,
    const float* __restrict__ v,
    float* __restrict__ ctx)
{
    extern __shared__ float smem[];
    float* kt = smem;                 // [256][64]
    float* vt = smem + 256 * 64;      // [256][64]

    const int c  = blockIdx.x;
    const int hh = blockIdx.y;
    const int bb = blockIdx.z;
    const int xq = threadIdx.x;
    const int pos = c * WINSZ + xq;

    // load this thread's (roped, scaled) query row
    const float* qrow = q + ((size_t)(bb * SEQ + pos)) * EMB + hh * HDIM;
    float qr[64];
#pragma unroll
    for (int i = 0; i < 16; i++)
        *(float4*)&qr[i * 4] = *(const float4*)&qrow[i * 4];

    float acc[64];
#pragma unroll
    for (int i = 0; i < 64; i++) acc[i] = 0.0f;
    float mval = -1e30f, l = 0.0f;

    // valid y range: y >= xq, y <= xq+512, kpos = c*256 + y - 256 in [0, SEQ)
    int ylo = xq;
    int lo_b = WINSZ - c * WINSZ;
    if (ylo < lo_b) ylo = lo_b;
    int yhi = xq + 2 * WINSZ;
    int hi_b = SEQ - c * WINSZ + WINSZ - 1;   // y <= this from kpos < SEQ
    if (hi_b > 767) hi_b = 767;
    if (yhi > hi_b) yhi = hi_b;

    for (int tile = 0; tile < 3; tile++) {
        const int ybase = tile * 256;
        // cooperative K/V tile load (256 rows x 16 float4)
        for (int i = threadIdx.x; i < 256 * 16; i += 256) {
            int row = i >> 4;
            int c4  = i & 15;
            int kpos = c * WINSZ + ybase + row - WINSZ;
            float4 kv = make_float4(0.f, 0.f, 0.f, 0.f);
            float4 vv = kv;
            if (kpos >= 0 && kpos < SEQ) {
                size_t off = ((size_t)(bb * SEQ + kpos)) * EMB + hh * HDIM + c4 * 4;
                kv = *(const float4*)&k[off];
                vv = *(const float4*)&v[off];
            }
            *(float4*)&kt[row * 64 + c4 * 4] = kv;
            *(float4*)&vt[row * 64 + c4 * 4] = vv;
        }
        __syncthreads();

        int y0 = ylo > ybase ? ylo : ybase;
        int y1 = yhi < (ybase + 255) ? yhi : (ybase + 255);
        for (int y = y0; y <= y1; y++) {
            const float* kr = &kt[(y - ybase) * 64];
            float s = 0.0f;
#pragma unroll
            for (int i = 0; i < 16; i++) {
                float4 kk4 = *(const float4*)&kr[i * 4];
                s = fmaf(qr[i * 4 + 0], kk4.x, s);
                s = fmaf(qr[i * 4 + 1], kk4.y, s);
                s = fmaf(qr[i * 4 + 2], kk4.z, s);
                s = fmaf(qr[i * 4 + 3], kk4.w, s);
            }
            float mnew = fmaxf(mval, s);
            float corr = __expf(mval - mnew);
            float p    = __expf(s - mnew);
            mval = mnew;
            l = l * corr + p;
            const float* vr = &vt[(y - ybase) * 64];
#pragma unroll
            for (int i = 0; i < 16; i++) {
                float4 vv4 = *(const float4*)&vr[i * 4];
                acc[i * 4 + 0] = fmaf(acc[i * 4 + 0], corr, p * vv4.x);
                acc[i * 4 + 1] = fmaf(acc[i * 4 + 1], corr, p * vv4.y);
                acc[i * 4 + 2] = fmaf(acc[i * 4 + 2], corr, p * vv4.z);
                acc[i * 4 + 3] = fmaf(acc[i * 4 + 3], corr, p * vv4.w);
            }
        }
        __syncthreads();
    }

    float inv_l = 1.0f / l;
    float* orow = ctx + ((size_t)(bb * SEQ + pos)) * EMB + hh * HDIM;
#pragma unroll
    for (int i = 0; i < 16; i++) {
        float4 o;
        o.x = acc[i * 4 + 0] * inv_l;
        o.y = acc[i * 4 + 1] * inv_l;
        o.z = acc[i * 4 + 2] * inv_l;
        o.w = acc[i * 4 + 3] * inv_l;
        *(float4*)&orow[i * 4] = o;
    }
}

// ---------------------------------------------------------------------------
extern "C" void kernel_launch(void* const* d_in, const int* in_sizes, int n_in,
                              void* d_out, int out_size)
{
    const float* x  = (const float*)d_in[0];
    const float* Wq = (const float*)d_in[1];
    const float* bq = (const float*)d_in[2];
    const float* Wk = (const float*)d_in[3];
    const float* bk = (const float*)d_in[4];
    const float* Wv = (const float*)d_in[5];
    const float* bv = (const float*)d_in[6];
    const float* Wo = (const float*)d_in[7];
    const float* bo = (const float*)d_in[8];
    float* out = (float*)d_out;

    float *q, *k, *v, *ctx;
    cudaGetSymbolAddress((void**)&q,   g_q);
    cudaGetSymbolAddress((void**)&k,   g_k);
    cudaGetSymbolAddress((void**)&v,   g_v);
    cudaGetSymbolAddress((void**)&ctx, g_ctx);

    const int attn_smem = 2 * 256 * HDIM * (int)sizeof(float);   // 128 KB
    cudaFuncSetAttribute(attn_kernel,
                         cudaFuncAttributeMaxDynamicSharedMemorySize, attn_smem);

    dim3 gemm_grid(EMB / 128, M_TOTAL / 128);

    sgemm_bias_kernel<<<gemm_grid, 256>>>(x, Wq, bq, q, M_TOTAL, EMB, EMB);
    sgemm_bias_kernel<<<gemm_grid, 256>>>(x, Wk, bk, k, M_TOTAL, EMB, EMB);
    sgemm_bias_kernel<<<gemm_grid, 256>>>(x, Wv, bv, v, M_TOTAL, EMB, EMB);

    const int pairs = M_TOTAL * EMB / 2;
    rope_kernel<<<(pairs + 255) / 256, 256>>>(q, 0.125f, pairs);  // /sqrt(64)
    rope_kernel<<<(pairs + 255) / 256, 256>>>(k, 1.0f, pairs);

    attn_kernel<<<dim3(NCHUNK, NHEADS, BATCH), 256, attn_smem>>>(q, k, v, ctx);

    sgemm_bias_kernel<<<gemm_grid, 256>>>(ctx, Wo, bo, out, M_TOTAL, EMB, EMB);
}

// round 2
// speedup vs baseline: 1.3807x; 1.3807x over previous
#include <cuda_runtime.h>
#include <math.h>
#include <stdint.h>

#define SEQ     4096
#define BATCH   2
#define EMB     1024
#define NHEADS  16
#define HDIM    64
#define WINSZ   256
#define NCHUNK  (SEQ / WINSZ)      // 16
#define M_TOTAL (BATCH * SEQ)      // 8192

// Scratch (allocation-free rule: __device__ globals)
__device__ float g_q[(size_t)M_TOTAL * EMB];
__device__ float g_k[(size_t)M_TOTAL * EMB];
__device__ float g_v[(size_t)M_TOTAL * EMB];
__device__ float g_ctx[(size_t)M_TOTAL * EMB];

// ---------------------------------------------------------------------------
// TF32 tensor-core GEMM: C[M,N] = A[M,K] @ B[N,K]^T + bias[N]
// 128x128x32 block tile, 8 warps (2x4), warp tile 64x32, m16n8k8 tf32 mma.
// A and B tiles stored in natural row-major [row][k] with padded stride 36:
// ldmatrix.m8n8.x4.b16 on 16B (4-tf32) segments yields the exact tf32
// fragment layouts, conflict-free.
// ---------------------------------------------------------------------------
#define BM 128
#define BN 128
#define BKK 32
#define LDST 36                         // padded floats per smem row
#define BUF_FLOATS (128 * LDST)         // 4608 floats per buffer
#define BUF_BYTES  (BUF_FLOATS * 4)     // 18432 B

__device__ __forceinline__ uint32_t f2tf(float x) {
    uint32_t u;
    asm("cvt.rna.tf32.f32 %0, %1;" : "=r"(u) : "f"(x));
    return u;
}

#define LDSM4(d, addr) \
    asm volatile("ldmatrix.sync.aligned.m8n8.x4.b16 {%0,%1,%2,%3}, [%4];" \
        : "=r"((d)[0]), "=r"((d)[1]), "=r"((d)[2]), "=r"((d)[3]) : "r"(addr))

#define MMA_TF32(c, a, b0_, b1_) \
    asm volatile("mma.sync.aligned.m16n8k8.row.col.f32.tf32.tf32.f32 " \
        "{%0,%1,%2,%3},{%4,%5,%6,%7},{%8,%9},{%0,%1,%2,%3};" \
        : "+f"((c)[0]), "+f"((c)[1]), "+f"((c)[2]), "+f"((c)[3]) \
        : "r"((a)[0]), "r"((a)[1]), "r"((a)[2]), "r"((a)[3]), \
          "r"(b0_), "r"(b1_))

__global__ __launch_bounds__(256, 1) void gemm_tf32_kernel(
    const float* __restrict__ A,
    const float* __restrict__ B,      // [N, K] row-major (weight)
    const float* __restrict__ bias,   // [N]
    float* __restrict__ C,
    int M, int N, int K)
{
    extern __shared__ float sm[];
    float* smA = sm;                      // [2][BUF_FLOATS]
    float* smB = sm + 2 * BUF_FLOATS;     // [2][BUF_FLOATS]

    const int tid  = threadIdx.x;
    const int warp = tid >> 5;
    const int lane = tid & 31;
    const int wm = warp >> 2;             // 0..1
    const int wn = warp & 3;              // 0..3
    const int m0 = blockIdx.y * BM;
    const int n0 = blockIdx.x * BN;

    const uint32_t smA_u = (uint32_t)__cvta_generic_to_shared(smA);
    const uint32_t smB_u = (uint32_t)__cvta_generic_to_shared(smB);

    // ldmatrix per-lane byte offsets within a buffer
    const int mat = lane >> 3, r = lane & 7;
    uint32_t offA[4], offB[2];
#pragma unroll
    for (int mt = 0; mt < 4; mt++)
        offA[mt] = (uint32_t)(((wm * 64 + mt * 16 + (mat & 1) * 8 + r) * LDST
                              + (mat >> 1) * 4) * 4);
#pragma unroll
    for (int nt2 = 0; nt2 < 2; nt2++)
        offB[nt2] = (uint32_t)(((wn * 32 + nt2 * 16 + (mat >> 1) * 8 + r) * LDST
                               + (mat & 1) * 4) * 4);

    // global->smem mapping: float4 id f = tid + 256*j; row = f/8, col4 = f%8
    int grow[4], gcol[4];
#pragma unroll
    for (int j = 0; j < 4; j++) {
        int f = tid + 256 * j;
        grow[j] = f >> 3;
        gcol[j] = (f & 7) * 4;
    }

    float acc[4][4][4];
#pragma unroll
    for (int mt = 0; mt < 4; mt++)
#pragma unroll
        for (int nt = 0; nt < 4; nt++)
#pragma unroll
            for (int i = 0; i < 4; i++) acc[mt][nt][i] = 0.0f;

    const int ntiles = K / BKK;
    float4 ra[4], rb[4];

    // prologue: load tile 0
#pragma unroll
    for (int j = 0; j < 4; j++) {
        ra[j] = *(const float4*)(A + (size_t)(m0 + grow[j]) * K + gcol[j]);
        rb[j] = *(const float4*)(B + (size_t)(n0 + grow[j]) * K + gcol[j]);
    }
#pragma unroll
    for (int j = 0; j < 4; j++) {
        float* dA = smA + grow[j] * LDST + gcol[j];
        float* dB = smB + grow[j] * LDST + gcol[j];
        dA[0] = __uint_as_float(f2tf(ra[j].x)); dA[1] = __uint_as_float(f2tf(ra[j].y));
        dA[2] = __uint_as_float(f2tf(ra[j].z)); dA[3] = __uint_as_float(f2tf(ra[j].w));
        dB[0] = __uint_as_float(f2tf(rb[j].x)); dB[1] = __uint_as_float(f2tf(rb[j].y));
        dB[2] = __uint_as_float(f2tf(rb[j].z)); dB[3] = __uint_as_float(f2tf(rb[j].w));
    }
    __syncthreads();

    for (int t = 0; t < ntiles; t++) {
        const int buf = t & 1;
        const bool pf = (t + 1 < ntiles);
        if (pf) {
            const int k0 = (t + 1) * BKK;
#pragma unroll
            for (int j = 0; j < 4; j++) {
                ra[j] = *(const float4*)(A + (size_t)(m0 + grow[j]) * K + k0 + gcol[j]);
                rb[j] = *(const float4*)(B + (size_t)(n0 + grow[j]) * K + k0 + gcol[j]);
            }
        }

        const uint32_t baseA = smA_u + buf * BUF_BYTES;
        const uint32_t baseB = smB_u + buf * BUF_BYTES;
#pragma unroll
        for (int kk = 0; kk < 4; kk++) {
            uint32_t af[4][4], bf[2][4];
#pragma unroll
            for (int mt = 0; mt < 4; mt++)
                LDSM4(af[mt], baseA + offA[mt] + kk * 32);
#pragma unroll
            for (int nt2 = 0; nt2 < 2; nt2++)
                LDSM4(bf[nt2], baseB + offB[nt2] + kk * 32);
#pragma unroll
            for (int mt = 0; mt < 4; mt++)
#pragma unroll
                for (int nt = 0; nt < 4; nt++)
                    MMA_TF32(acc[mt][nt], af[mt],
                             bf[nt >> 1][(nt & 1) * 2], bf[nt >> 1][(nt & 1) * 2 + 1]);
        }

        if (pf) {
            float* sA = smA + (buf ^ 1) * BUF_FLOATS;
            float* sB = smB + (buf ^ 1) * BUF_FLOATS;
#pragma unroll
            for (int j = 0; j < 4; j++) {
                float* dA = sA + grow[j] * LDST + gcol[j];
                float* dB = sB + grow[j] * LDST + gcol[j];
                dA[0] = __uint_as_float(f2tf(ra[j].x)); dA[1] = __uint_as_float(f2tf(ra[j].y));
                dA[2] = __uint_as_float(f2tf(ra[j].z)); dA[3] = __uint_as_float(f2tf(ra[j].w));
                dB[0] = __uint_as_float(f2tf(rb[j].x)); dB[1] = __uint_as_float(f2tf(rb[j].y));
                dB[2] = __uint_as_float(f2tf(rb[j].z)); dB[3] = __uint_as_float(f2tf(rb[j].w));
            }
        }
        __syncthreads();
    }

    // epilogue: C = acc + bias
#pragma unroll
    for (int mt = 0; mt < 4; mt++) {
        int gr = m0 + wm * 64 + mt * 16 + (lane >> 2);
#pragma unroll
        for (int nt = 0; nt < 4; nt++) {
            int gc = n0 + wn * 32 + nt * 8 + (lane & 3) * 2;
            float b0 = bias[gc], b1 = bias[gc + 1];
            float2 v0 = make_float2(acc[mt][nt][0] + b0, acc[mt][nt][1] + b1);
            float2 v1 = make_float2(acc[mt][nt][2] + b0, acc[mt][nt][3] + b1);
            *(float2*)&C[(size_t)gr * EMB + gc] = v0;
            *(float2*)&C[(size_t)(gr + 8) * EMB + gc] = v1;
        }
    }
}

// ---------------------------------------------------------------------------
// RoPE (reference quirk: angle = head_index * inv[t % 32]; interleaved x2).
// ---------------------------------------------------------------------------
__global__ void rope_kernel(float* __restrict__ x, float scale, int total_pairs)
{
    int pid = blockIdx.x * blockDim.x + threadIdx.x;
    if (pid >= total_pairs) return;
    int base = pid << 1;
    int col = base & (EMB - 1);
    int hh = col >> 6;          // head index
    int t  = col & 63;          // even dim index within head
    int j0 = t & 31;
    int j1 = (t + 1) & 31;
    const float kln = 0.28782313662425572f;   // ln(10000)/32
    float a0 = (float)hh * __expf(-kln * (float)j0);
    float a1 = (float)hh * __expf(-kln * (float)j1);
    float s0, c0, s1, c1;
    sincosf(a0, &s0, &c0);
    sincosf(a1, &s1, &c1);
    float x0 = x[base], x1 = x[base + 1];
    x[base]     = (x0 * c0 - x1 * s0) * scale;
    x[base + 1] = (x1 * c1 + x0 * s1) * scale;
}

// ---------------------------------------------------------------------------
// Windowed attention. Block = (chunk, head, batch). 256 threads = 256 queries.
// K/V band (768 keys) streamed in 3 tiles of 256 through dynamic smem.
// ---------------------------------------------------------------------------
__global__ __launch_bounds__(256, 1) void attn_kernel(
    const float* __restrict__ q,
    const float* __restrict__ k,
    const float* __restrict__ v,
    float* __restrict__ ctx)
{
    extern __shared__ float smem[];
    float* kt = smem;                 // [256][64]
    float* vt = smem + 256 * 64;      // [256][64]

    const int c  = blockIdx.x;
    const int hh = blockIdx.y;
    const int bb = blockIdx.z;
    const int xq = threadIdx.x;
    const int pos = c * WINSZ + xq;

    const float* qrow = q + ((size_t)(bb * SEQ + pos)) * EMB + hh * HDIM;
    float qr[64];
#pragma unroll
    for (int i = 0; i < 16; i++)
        *(float4*)&qr[i * 4] = *(const float4*)&qrow[i * 4];

    float acc[64];
#pragma unroll
    for (int i = 0; i < 64; i++) acc[i] = 0.0f;
    float mval = -1e30f, l = 0.0f;

    int ylo = xq;
    int lo_b = WINSZ - c * WINSZ;
    if (ylo < lo_b) ylo = lo_b;
    int yhi = xq + 2 * WINSZ;
    int hi_b = SEQ - c * WINSZ + WINSZ - 1;
    if (hi_b > 767) hi_b = 767;
    if (yhi > hi_b) yhi = hi_b;

    for (int tile = 0; tile < 3; tile++) {
        const int ybase = tile * 256;
        for (int i = threadIdx.x; i < 256 * 16; i += 256) {
            int row = i >> 4;
            int c4  = i & 15;
            int kpos = c * WINSZ + ybase + row - WINSZ;
            float4 kv = make_float4(0.f, 0.f, 0.f, 0.f);
            float4 vv = kv;
            if (kpos >= 0 && kpos < SEQ) {
                size_t off = ((size_t)(bb * SEQ + kpos)) * EMB + hh * HDIM + c4 * 4;
                kv = *(const float4*)&k[off];
                vv = *(const float4*)&v[off];
            }
            *(float4*)&kt[row * 64 + c4 * 4] = kv;
            *(float4*)&vt[row * 64 + c4 * 4] = vv;
        }
        __syncthreads();

        int y0 = ylo > ybase ? ylo : ybase;
        int y1 = yhi < (ybase + 255) ? yhi : (ybase + 255);
        for (int y = y0; y <= y1; y++) {
            const float* kr = &kt[(y - ybase) * 64];
            float s = 0.0f;
#pragma unroll
            for (int i = 0; i < 16; i++) {
                float4 kk4 = *(const float4*)&kr[i * 4];
                s = fmaf(qr[i * 4 + 0], kk4.x, s);
                s = fmaf(qr[i * 4 + 1], kk4.y, s);
                s = fmaf(qr[i * 4 + 2], kk4.z, s);
                s = fmaf(qr[i * 4 + 3], kk4.w, s);
            }
            float mnew = fmaxf(mval, s);
            float corr = __expf(mval - mnew);
            float p    = __expf(s - mnew);
            mval = mnew;
            l = l * corr + p;
            const float* vr = &vt[(y - ybase) * 64];
#pragma unroll
            for (int i = 0; i < 16; i++) {
                float4 vv4 = *(const float4*)&vr[i * 4];
                acc[i * 4 + 0] = fmaf(acc[i * 4 + 0], corr, p * vv4.x);
                acc[i * 4 + 1] = fmaf(acc[i * 4 + 1], corr, p * vv4.y);
                acc[i * 4 + 2] = fmaf(acc[i * 4 + 2], corr, p * vv4.z);
                acc[i * 4 + 3] = fmaf(acc[i * 4 + 3], corr, p * vv4.w);
            }
        }
        __syncthreads();
    }

    float inv_l = 1.0f / l;
    float* orow = ctx + ((size_t)(bb * SEQ + pos)) * EMB + hh * HDIM;
#pragma unroll
    for (int i = 0; i < 16; i++) {
        float4 o;
        o.x = acc[i * 4 + 0] * inv_l;
        o.y = acc[i * 4 + 1] * inv_l;
        o.z = acc[i * 4 + 2] * inv_l;
        o.w = acc[i * 4 + 3] * inv_l;
        *(float4*)&orow[i * 4] = o;
    }
}

// ---------------------------------------------------------------------------
extern "C" void kernel_launch(void* const* d_in, const int* in_sizes, int n_in,
                              void* d_out, int out_size)
{
    const float* x  = (const float*)d_in[0];
    const float* Wq = (const float*)d_in[1];
    const float* bq = (const float*)d_in[2];
    const float* Wk = (const float*)d_in[3];
    const float* bk = (const float*)d_in[4];
    const float* Wv = (const float*)d_in[5];
    const float* bv = (const float*)d_in[6];
    const float* Wo = (const float*)d_in[7];
    const float* bo = (const float*)d_in[8];
    float* out = (float*)d_out;

    float *q, *k, *v, *ctx;
    cudaGetSymbolAddress((void**)&q,   g_q);
    cudaGetSymbolAddress((void**)&k,   g_k);
    cudaGetSymbolAddress((void**)&v,   g_v);
    cudaGetSymbolAddress((void**)&ctx, g_ctx);

    const int attn_smem = 2 * 256 * HDIM * (int)sizeof(float);   // 128 KB
    cudaFuncSetAttribute(attn_kernel,
                         cudaFuncAttributeMaxDynamicSharedMemorySize, attn_smem);
    const int gemm_smem = 4 * BUF_BYTES;                          // 73728 B
    cudaFuncSetAttribute(gemm_tf32_kernel,
                         cudaFuncAttributeMaxDynamicSharedMemorySize, gemm_smem);

    dim3 gemm_grid(EMB / BN, M_TOTAL / BM);

    gemm_tf32_kernel<<<gemm_grid, 256, gemm_smem>>>(x, Wq, bq, q, M_TOTAL, EMB, EMB);
    gemm_tf32_kernel<<<gemm_grid, 256, gemm_smem>>>(x, Wk, bk, k, M_TOTAL, EMB, EMB);
    gemm_tf32_kernel<<<gemm_grid, 256, gemm_smem>>>(x, Wv, bv, v, M_TOTAL, EMB, EMB);

    const int pairs = M_TOTAL * EMB / 2;
    rope_kernel<<<(pairs + 255) / 256, 256>>>(q, 0.125f, pairs);  // /sqrt(64)
    rope_kernel<<<(pairs + 255) / 256, 256>>>(k, 1.0f, pairs);

    attn_kernel<<<dim3(NCHUNK, NHEADS, BATCH), 256, attn_smem>>>(q, k, v, ctx);

    gemm_tf32_kernel<<<gemm_grid, 256, gemm_smem>>>(ctx, Wo, bo, out, M_TOTAL, EMB, EMB);
}

// round 4
// speedup vs baseline: 3.1722x; 2.2976x over previous
#include <cuda_runtime.h>
#include <math.h>
#include <stdint.h>

#define SEQ     4096
#define BATCH   2
#define EMB     1024
#define NHEADS  16
#define HDIM    64
#define WINSZ   256
#define NCHUNK  (SEQ / WINSZ)      // 16
#define M_TOTAL (BATCH * SEQ)      // 8192
#define KLN     0.28782313662425572f   // ln(10000)/32

// Scratch (allocation-free rule: __device__ globals)
__device__ float g_q[(size_t)M_TOTAL * EMB];
__device__ float g_k[(size_t)M_TOTAL * EMB];
__device__ float g_v[(size_t)M_TOTAL * EMB];
__device__ float g_ctx[(size_t)M_TOTAL * EMB];

// ---------------------------------------------------------------------------
// TF32 tensor-core GEMM: C[M,N] = A[M,K] @ B[N,K]^T + bias[N], optional fused
// RoPE rotation on (even,odd) column pairs in the epilogue.
// 128x128x32 block tile, 8 warps (2x4), warp tile 64x32, m16n8k8 tf32 mma.
// ---------------------------------------------------------------------------
#define BM 128
#define BN 128
#define BKK 32
#define LDST 36                         // padded floats per smem row
#define BUF_FLOATS (128 * LDST)         // 4608 floats per buffer
#define BUF_BYTES  (BUF_FLOATS * 4)     // 18432 B

__device__ __forceinline__ uint32_t f2tf(float x) {
    uint32_t u;
    asm("cvt.rna.tf32.f32 %0, %1;" : "=r"(u) : "f"(x));
    return u;
}

#define LDSM4(d, addr) \
    asm volatile("ldmatrix.sync.aligned.m8n8.x4.b16 {%0,%1,%2,%3}, [%4];" \
        : "=r"((d)[0]), "=r"((d)[1]), "=r"((d)[2]), "=r"((d)[3]) : "r"(addr))

#define MMA_TF32(c, a, b0_, b1_) \
    asm volatile("mma.sync.aligned.m16n8k8.row.col.f32.tf32.tf32.f32 " \
        "{%0,%1,%2,%3},{%4,%5,%6,%7},{%8,%9},{%0,%1,%2,%3};" \
        : "+f"((c)[0]), "+f"((c)[1]), "+f"((c)[2]), "+f"((c)[3]) \
        : "r"((a)[0]), "r"((a)[1]), "r"((a)[2]), "r"((a)[3]), \
          "r"(b0_), "r"(b1_))

__global__ __launch_bounds__(256, 1) void gemm_tf32_kernel(
    const float* __restrict__ A,
    const float* __restrict__ B,      // [N, K] row-major (weight)
    const float* __restrict__ bias,   // [N]
    float* __restrict__ C,
    int M, int N, int K,
    int rope_mode, float rope_scale)
{
    extern __shared__ float sm[];
    float* smA = sm;                      // [2][BUF_FLOATS]
    float* smB = sm + 2 * BUF_FLOATS;     // [2][BUF_FLOATS]

    const int tid  = threadIdx.x;
    const int warp = tid >> 5;
    const int lane = tid & 31;
    const int wm = warp >> 2;             // 0..1
    const int wn = warp & 3;              // 0..3
    const int m0 = blockIdx.y * BM;
    const int n0 = blockIdx.x * BN;

    const uint32_t smA_u = (uint32_t)__cvta_generic_to_shared(smA);
    const uint32_t smB_u = (uint32_t)__cvta_generic_to_shared(smB);

    const int mat = lane >> 3, r = lane & 7;
    uint32_t offA[4], offB[2];
#pragma unroll
    for (int mt = 0; mt < 4; mt++)
        offA[mt] = (uint32_t)(((wm * 64 + mt * 16 + (mat & 1) * 8 + r) * LDST
                              + (mat >> 1) * 4) * 4);
#pragma unroll
    for (int nt2 = 0; nt2 < 2; nt2++)
        offB[nt2] = (uint32_t)(((wn * 32 + nt2 * 16 + (mat >> 1) * 8 + r) * LDST
                               + (mat & 1) * 4) * 4);

    int grow[4], gcol[4];
#pragma unroll
    for (int j = 0; j < 4; j++) {
        int f = tid + 256 * j;
        grow[j] = f >> 3;
        gcol[j] = (f & 7) * 4;
    }

    float acc[4][4][4];
#pragma unroll
    for (int mt = 0; mt < 4; mt++)
#pragma unroll
        for (int nt = 0; nt < 4; nt++)
#pragma unroll
            for (int i = 0; i < 4; i++) acc[mt][nt][i] = 0.0f;

    const int ntiles = K / BKK;
    float4 ra[4], rb[4];

#pragma unroll
    for (int j = 0; j < 4; j++) {
        ra[j] = *(const float4*)(A + (size_t)(m0 + grow[j]) * K + gcol[j]);
        rb[j] = *(const float4*)(B + (size_t)(n0 + grow[j]) * K + gcol[j]);
    }
#pragma unroll
    for (int j = 0; j < 4; j++) {
        float* dA = smA + grow[j] * LDST + gcol[j];
        float* dB = smB + grow[j] * LDST + gcol[j];
        dA[0] = __uint_as_float(f2tf(ra[j].x)); dA[1] = __uint_as_float(f2tf(ra[j].y));
        dA[2] = __uint_as_float(f2tf(ra[j].z)); dA[3] = __uint_as_float(f2tf(ra[j].w));
        dB[0] = __uint_as_float(f2tf(rb[j].x)); dB[1] = __uint_as_float(f2tf(rb[j].y));
        dB[2] = __uint_as_float(f2tf(rb[j].z)); dB[3] = __uint_as_float(f2tf(rb[j].w));
    }
    __syncthreads();

    for (int t = 0; t < ntiles; t++) {
        const int buf = t & 1;
        const bool pf = (t + 1 < ntiles);
        if (pf) {
            const int k0 = (t + 1) * BKK;
#pragma unroll
            for (int j = 0; j < 4; j++) {
                ra[j] = *(const float4*)(A + (size_t)(m0 + grow[j]) * K + k0 + gcol[j]);
                rb[j] = *(const float4*)(B + (size_t)(n0 + grow[j]) * K + k0 + gcol[j]);
            }
        }

        const uint32_t baseA = smA_u + buf * BUF_BYTES;
        const uint32_t baseB = smB_u + buf * BUF_BYTES;
#pragma unroll
        for (int kk = 0; kk < 4; kk++) {
            uint32_t af[4][4], bf[2][4];
#pragma unroll
            for (int mt = 0; mt < 4; mt++)
                LDSM4(af[mt], baseA + offA[mt] + kk * 32);
#pragma unroll
            for (int nt2 = 0; nt2 < 2; nt2++)
                LDSM4(bf[nt2], baseB + offB[nt2] + kk * 32);
#pragma unroll
            for (int mt = 0; mt < 4; mt++)
#pragma unroll
                for (int nt = 0; nt < 4; nt++)
                    MMA_TF32(acc[mt][nt], af[mt],
                             bf[nt >> 1][(nt & 1) * 2], bf[nt >> 1][(nt & 1) * 2 + 1]);
        }

        if (pf) {
            float* sA = smA + (buf ^ 1) * BUF_FLOATS;
            float* sB = smB + (buf ^ 1) * BUF_FLOATS;
#pragma unroll
            for (int j = 0; j < 4; j++) {
                float* dA = sA + grow[j] * LDST + gcol[j];
                float* dB = sB + grow[j] * LDST + gcol[j];
                dA[0] = __uint_as_float(f2tf(ra[j].x)); dA[1] = __uint_as_float(f2tf(ra[j].y));
                dA[2] = __uint_as_float(f2tf(ra[j].z)); dA[3] = __uint_as_float(f2tf(ra[j].w));
                dB[0] = __uint_as_float(f2tf(rb[j].x)); dB[1] = __uint_as_float(f2tf(rb[j].y));
                dB[2] = __uint_as_float(f2tf(rb[j].z)); dB[3] = __uint_as_float(f2tf(rb[j].w));
            }
        }
        __syncthreads();
    }

    // epilogue: C = acc + bias, optionally RoPE-rotated (angles depend on col)
#pragma unroll
    for (int nt = 0; nt < 4; nt++) {
        int gc = n0 + wn * 32 + nt * 8 + (lane & 3) * 2;   // even column
        float b0 = bias[gc], b1 = bias[gc + 1];
        float s0 = 0.f, c0 = 1.f, s1 = 0.f, c1 = 1.f;
        if (rope_mode) {
            int hd = gc >> 6;           // head index
            int j0 = gc & 31;           // inv index (even)
            float a0 = (float)hd * __expf(-KLN * (float)j0);
            float a1 = (float)hd * __expf(-KLN * (float)(j0 + 1));
            sincosf(a0, &s0, &c0);
            sincosf(a1, &s1, &c1);
        }
#pragma unroll
        for (int mt = 0; mt < 4; mt++) {
            int gr = m0 + wm * 64 + mt * 16 + (lane >> 2);
#pragma unroll
            for (int half = 0; half < 2; half++) {
                float x0 = acc[mt][nt][half * 2 + 0] + b0;
                float x1 = acc[mt][nt][half * 2 + 1] + b1;
                float y0 = x0, y1 = x1;
                if (rope_mode) {
                    y0 = (x0 * c0 - x1 * s0) * rope_scale;
                    y1 = (x1 * c1 + x0 * s1) * rope_scale;
                }
                *(float2*)&C[(size_t)(gr + half * 8) * EMB + gc] = make_float2(y0, y1);
            }
        }
    }
}

// ---------------------------------------------------------------------------
// Windowed attention, warp-synchronous over keys.
// Block = (chunk, head, batch), 256 threads = 256 queries; warp w owns
// queries [w*32, w*32+32). All lanes of a warp visit the SAME key y each
// step -> kt/vt smem reads are broadcasts (no bank conflicts).
// Deferred-rescale online softmax; invalid lanes skip V accumulation.
// ---------------------------------------------------------------------------
__global__ __launch_bounds__(256, 1) void attn_kernel(
    const float* __restrict__ q,
    const float* __restrict__ k,
    const float* __restrict__ v,
    float* __restrict__ ctx)
{
    extern __shared__ float smem[];
    float* kt = smem;                 // [256][64]
    float* vt = smem + 256 * 64;      // [256][64]

    const int c  = blockIdx.x;
    const int hh = blockIdx.y;
    const int bb = blockIdx.z;
    const int tid = threadIdx.x;
    const int w   = tid >> 5;
    const int xq  = tid;                  // query index within chunk
    const int pos = c * WINSZ + xq;

    const float* qrow = q + ((size_t)(bb * SEQ + pos)) * EMB + hh * HDIM;
    float qr[64];
#pragma unroll
    for (int i = 0; i < 16; i++)
        *(float4*)&qr[i * 4] = *(const float4*)&qrow[i * 4];

    float acc[64];
#pragma unroll
    for (int i = 0; i < 64; i++) acc[i] = 0.0f;
    float mval = -1e30f, l = 0.0f;

    // warp-uniform y bounds (kpos-range bounds are uniform across the block)
    int wy_lo = w * 32;
    int lob = WINSZ - c * WINSZ;                 // kpos >= 0
    if (wy_lo < lob) wy_lo = lob;
    int wy_hi = w * 32 + 31 + 2 * WINSZ;
    int hib = SEQ - 1 - c * WINSZ + WINSZ;       // kpos <= SEQ-1
    if (hib > 3 * WINSZ - 1) hib = 3 * WINSZ - 1;
    if (wy_hi > hib) wy_hi = hib;

    for (int tile = 0; tile < 3; tile++) {
        const int ybase = tile * 256;
        // cooperative K/V tile load (256 rows x 16 float4)
        for (int i = tid; i < 256 * 16; i += 256) {
            int row = i >> 4;
            int c4  = i & 15;
            int kpos = c * WINSZ + ybase + row - WINSZ;
            float4 kv = make_float4(0.f, 0.f, 0.f, 0.f);
            float4 vv = kv;
            if (kpos >= 0 && kpos < SEQ) {
                size_t off = ((size_t)(bb * SEQ + kpos)) * EMB + hh * HDIM + c4 * 4;
                kv = *(const float4*)&k[off];
                vv = *(const float4*)&v[off];
            }
            *(float4*)&kt[row * 64 + c4 * 4] = kv;
            *(float4*)&vt[row * 64 + c4 * 4] = vv;
        }
        __syncthreads();

        int y0 = wy_lo > ybase ? wy_lo : ybase;
        int y1 = wy_hi < (ybase + 255) ? wy_hi : (ybase + 255);
        for (int y = y0; y <= y1; y++) {
            const float* kr = &kt[(y - ybase) * 64];   // broadcast reads
            float p0 = 0.f, p1 = 0.f, p2 = 0.f, p3 = 0.f;
#pragma unroll
            for (int i = 0; i < 16; i++) {
                float4 kk4 = *(const float4*)&kr[i * 4];
                p0 = fmaf(qr[i * 4 + 0], kk4.x, p0);
                p1 = fmaf(qr[i * 4 + 1], kk4.y, p1);
                p2 = fmaf(qr[i * 4 + 2], kk4.z, p2);
                p3 = fmaf(qr[i * 4 + 3], kk4.w, p3);
            }
            float s = (p0 + p1) + (p2 + p3);
            bool valid = (unsigned)(y - xq) <= (unsigned)(2 * WINSZ);
            if (valid) {
                if (s > mval) {            // deferred rescale
                    float corr = __expf(mval - s);
                    l *= corr;
#pragma unroll
                    for (int i = 0; i < 64; i++) acc[i] *= corr;
                    mval = s;
                }
                float p = __expf(s - mval);
                l += p;
                const float* vr = &vt[(y - ybase) * 64];   // broadcast reads
#pragma unroll
                for (int i = 0; i < 16; i++) {
                    float4 vv4 = *(const float4*)&vr[i * 4];
                    acc[i * 4 + 0] = fmaf(p, vv4.x, acc[i * 4 + 0]);
                    acc[i * 4 + 1] = fmaf(p, vv4.y, acc[i * 4 + 1]);
                    acc[i * 4 + 2] = fmaf(p, vv4.z, acc[i * 4 + 2]);
                    acc[i * 4 + 3] = fmaf(p, vv4.w, acc[i * 4 + 3]);
                }
            }
        }
        __syncthreads();
    }

    float inv_l = 1.0f / l;
    float* orow = ctx + ((size_t)(bb * SEQ + pos)) * EMB + hh * HDIM;
#pragma unroll
    for (int i = 0; i < 16; i++) {
        float4 o;
        o.x = acc[i * 4 + 0] * inv_l;
        o.y = acc[i * 4 + 1] * inv_l;
        o.z = acc[i * 4 + 2] * inv_l;
        o.w = acc[i * 4 + 3] * inv_l;
        *(float4*)&orow[i * 4] = o;
    }
}

// ---------------------------------------------------------------------------
extern "C" void kernel_launch(void* const* d_in, const int* in_sizes, int n_in,
                              void* d_out, int out_size)
{
    const float* x  = (const float*)d_in[0];
    const float* Wq = (const float*)d_in[1];
    const float* bq = (const float*)d_in[2];
    const float* Wk = (const float*)d_in[3];
    const float* bk = (const float*)d_in[4];
    const float* Wv = (const float*)d_in[5];
    const float* bv = (const float*)d_in[6];
    const float* Wo = (const float*)d_in[7];
    const float* bo = (const float*)d_in[8];
    float* out = (float*)d_out;

    float *q, *k, *v, *ctx;
    cudaGetSymbolAddress((void**)&q,   g_q);
    cudaGetSymbolAddress((void**)&k,   g_k);
    cudaGetSymbolAddress((void**)&v,   g_v);
    cudaGetSymbolAddress((void**)&ctx, g_ctx);

    const int attn_smem = 2 * 256 * HDIM * (int)sizeof(float);   // 128 KB
    cudaFuncSetAttribute(attn_kernel,
                         cudaFuncAttributeMaxDynamicSharedMemorySize, attn_smem);
    const int gemm_smem = 4 * BUF_BYTES;                          // 73728 B
    cudaFuncSetAttribute(gemm_tf32_kernel,
                         cudaFuncAttributeMaxDynamicSharedMemorySize, gemm_smem);

    dim3 gemm_grid(EMB / BN, M_TOTAL / BM);

    // RoPE fused into Q/K projection epilogues (q also scaled by 1/sqrt(64))
    gemm_tf32_kernel<<<gemm_grid, 256, gemm_smem>>>(x, Wq, bq, q, M_TOTAL, EMB, EMB, 1, 0.125f);
    gemm_tf32_kernel<<<gemm_grid, 256, gemm_smem>>>(x, Wk, bk, k, M_TOTAL, EMB, EMB, 1, 1.0f);
    gemm_tf32_kernel<<<gemm_grid, 256, gemm_smem>>>(x, Wv, bv, v, M_TOTAL, EMB, EMB, 0, 1.0f);

    attn_kernel<<<dim3(NCHUNK, NHEADS, BATCH), 256, attn_smem>>>(q, k, v, ctx);

    gemm_tf32_kernel<<<gemm_grid, 256, gemm_smem>>>(ctx, Wo, bo, out, M_TOTAL, EMB, EMB, 0, 1.0f);
}

// round 5
// speedup vs baseline: 3.6294x; 1.1441x over previous
#include <cuda_runtime.h>
#include <math.h>
#include <stdint.h>

#define SEQ     4096
#define BATCH   2
#define EMB     1024
#define NHEADS  16
#define HDIM    64
#define WINSZ   256
#define NCHUNK  (SEQ / WINSZ)      // 16
#define M_TOTAL (BATCH * SEQ)      // 8192
#define KLN     0.28782313662425572f   // ln(10000)/32

// Scratch (allocation-free rule: __device__ globals)
__device__ float g_q[(size_t)M_TOTAL * EMB];
__device__ float g_k[(size_t)M_TOTAL * EMB];
__device__ float g_v[(size_t)M_TOTAL * EMB];
__device__ float g_ctx[(size_t)M_TOTAL * EMB];

// Packed f32x2 ops (Blackwell FFMA2 path — only reachable via PTX)
#define FMA_F32X2(out, a, b, c) \
    asm("fma.rn.f32x2 %0, %1, %2, %3;" : "=l"(out) : "l"(a), "l"(b), "l"(c))
#define ADD_F32X2(out, a, b) \
    asm("add.rn.f32x2 %0, %1, %2;" : "=l"(out) : "l"(a), "l"(b))
#define MUL_F32X2(out, a, b) \
    asm("mul.rn.f32x2 %0, %1, %2;" : "=l"(out) : "l"(a), "l"(b))
#define PACK_F32X2(out, lo, hi) \
    asm("mov.b64 %0, {%1, %2};" : "=l"(out) : "f"(lo), "f"(hi))
#define UNPACK_F32X2(lo, hi, in) \
    asm("mov.b64 {%0, %1}, %2;" : "=f"(lo), "=f"(hi) : "l"(in))

// ---------------------------------------------------------------------------
// TF32 tensor-core GEMM: C[M,N] = A[M,K] @ B[N,K]^T + bias[N], optional fused
// RoPE rotation on (even,odd) column pairs in the epilogue.
// 128x128x32 block tile, 8 warps (2x4), warp tile 64x32, m16n8k8 tf32 mma.
// ---------------------------------------------------------------------------
#define BM 128
#define BN 128
#define BKK 32
#define LDST 36                         // padded floats per smem row
#define BUF_FLOATS (128 * LDST)         // 4608 floats per buffer
#define BUF_BYTES  (BUF_FLOATS * 4)     // 18432 B

__device__ __forceinline__ uint32_t f2tf(float x) {
    uint32_t u;
    asm("cvt.rna.tf32.f32 %0, %1;" : "=r"(u) : "f"(x));
    return u;
}

#define LDSM4(d, addr) \
    asm volatile("ldmatrix.sync.aligned.m8n8.x4.b16 {%0,%1,%2,%3}, [%4];" \
        : "=r"((d)[0]), "=r"((d)[1]), "=r"((d)[2]), "=r"((d)[3]) : "r"(addr))

#define MMA_TF32(c, a, b0_, b1_) \
    asm volatile("mma.sync.aligned.m16n8k8.row.col.f32.tf32.tf32.f32 " \
        "{%0,%1,%2,%3},{%4,%5,%6,%7},{%8,%9},{%0,%1,%2,%3};" \
        : "+f"((c)[0]), "+f"((c)[1]), "+f"((c)[2]), "+f"((c)[3]) \
        : "r"((a)[0]), "r"((a)[1]), "r"((a)[2]), "r"((a)[3]), \
          "r"(b0_), "r"(b1_))

__global__ __launch_bounds__(256, 1) void gemm_tf32_kernel(
    const float* __restrict__ A,
    const float* __restrict__ B,      // [N, K] row-major (weight)
    const float* __restrict__ bias,   // [N]
    float* __restrict__ C,
    int M, int N, int K,
    int rope_mode, float rope_scale)
{
    extern __shared__ float sm[];
    float* smA = sm;                      // [2][BUF_FLOATS]
    float* smB = sm + 2 * BUF_FLOATS;     // [2][BUF_FLOATS]

    const int tid  = threadIdx.x;
    const int warp = tid >> 5;
    const int lane = tid & 31;
    const int wm = warp >> 2;             // 0..1
    const int wn = warp & 3;              // 0..3
    const int m0 = blockIdx.y * BM;
    const int n0 = blockIdx.x * BN;

    const uint32_t smA_u = (uint32_t)__cvta_generic_to_shared(smA);
    const uint32_t smB_u = (uint32_t)__cvta_generic_to_shared(smB);

    const int mat = lane >> 3, r = lane & 7;
    uint32_t offA[4], offB[2];
#pragma unroll
    for (int mt = 0; mt < 4; mt++)
        offA[mt] = (uint32_t)(((wm * 64 + mt * 16 + (mat & 1) * 8 + r) * LDST
                              + (mat >> 1) * 4) * 4);
#pragma unroll
    for (int nt2 = 0; nt2 < 2; nt2++)
        offB[nt2] = (uint32_t)(((wn * 32 + nt2 * 16 + (mat >> 1) * 8 + r) * LDST
                               + (mat & 1) * 4) * 4);

    int grow[4], gcol[4];
#pragma unroll
    for (int j = 0; j < 4; j++) {
        int f = tid + 256 * j;
        grow[j] = f >> 3;
        gcol[j] = (f & 7) * 4;
    }

    float acc[4][4][4];
#pragma unroll
    for (int mt = 0; mt < 4; mt++)
#pragma unroll
        for (int nt = 0; nt < 4; nt++)
#pragma unroll
            for (int i = 0; i < 4; i++) acc[mt][nt][i] = 0.0f;

    const int ntiles = K / BKK;
    float4 ra[4], rb[4];

#pragma unroll
    for (int j = 0; j < 4; j++) {
        ra[j] = *(const float4*)(A + (size_t)(m0 + grow[j]) * K + gcol[j]);
        rb[j] = *(const float4*)(B + (size_t)(n0 + grow[j]) * K + gcol[j]);
    }
#pragma unroll
    for (int j = 0; j < 4; j++) {
        float* dA = smA + grow[j] * LDST + gcol[j];
        float* dB = smB + grow[j] * LDST + gcol[j];
        dA[0] = __uint_as_float(f2tf(ra[j].x)); dA[1] = __uint_as_float(f2tf(ra[j].y));
        dA[2] = __uint_as_float(f2tf(ra[j].z)); dA[3] = __uint_as_float(f2tf(ra[j].w));
        dB[0] = __uint_as_float(f2tf(rb[j].x)); dB[1] = __uint_as_float(f2tf(rb[j].y));
        dB[2] = __uint_as_float(f2tf(rb[j].z)); dB[3] = __uint_as_float(f2tf(rb[j].w));
    }
    __syncthreads();

    for (int t = 0; t < ntiles; t++) {
        const int buf = t & 1;
        const bool pf = (t + 1 < ntiles);
        if (pf) {
            const int k0 = (t + 1) * BKK;
#pragma unroll
            for (int j = 0; j < 4; j++) {
                ra[j] = *(const float4*)(A + (size_t)(m0 + grow[j]) * K + k0 + gcol[j]);
                rb[j] = *(const float4*)(B + (size_t)(n0 + grow[j]) * K + k0 + gcol[j]);
            }
        }

        const uint32_t baseA = smA_u + buf * BUF_BYTES;
        const uint32_t baseB = smB_u + buf * BUF_BYTES;
#pragma unroll
        for (int kk = 0; kk < 4; kk++) {
            uint32_t af[4][4], bf[2][4];
#pragma unroll
            for (int mt = 0; mt < 4; mt++)
                LDSM4(af[mt], baseA + offA[mt] + kk * 32);
#pragma unroll
            for (int nt2 = 0; nt2 < 2; nt2++)
                LDSM4(bf[nt2], baseB + offB[nt2] + kk * 32);
#pragma unroll
            for (int mt = 0; mt < 4; mt++)
#pragma unroll
                for (int nt = 0; nt < 4; nt++)
                    MMA_TF32(acc[mt][nt], af[mt],
                             bf[nt >> 1][(nt & 1) * 2], bf[nt >> 1][(nt & 1) * 2 + 1]);
        }

        if (pf) {
            float* sA = smA + (buf ^ 1) * BUF_FLOATS;
            float* sB = smB + (buf ^ 1) * BUF_FLOATS;
#pragma unroll
            for (int j = 0; j < 4; j++) {
                float* dA = sA + grow[j] * LDST + gcol[j];
                float* dB = sB + grow[j] * LDST + gcol[j];
                dA[0] = __uint_as_float(f2tf(ra[j].x)); dA[1] = __uint_as_float(f2tf(ra[j].y));
                dA[2] = __uint_as_float(f2tf(ra[j].z)); dA[3] = __uint_as_float(f2tf(ra[j].w));
                dB[0] = __uint_as_float(f2tf(rb[j].x)); dB[1] = __uint_as_float(f2tf(rb[j].y));
                dB[2] = __uint_as_float(f2tf(rb[j].z)); dB[3] = __uint_as_float(f2tf(rb[j].w));
            }
        }
        __syncthreads();
    }

    // epilogue: C = acc + bias, optionally RoPE-rotated (angles depend on col)
#pragma unroll
    for (int nt = 0; nt < 4; nt++) {
        int gc = n0 + wn * 32 + nt * 8 + (lane & 3) * 2;   // even column
        float b0 = bias[gc], b1 = bias[gc + 1];
        float s0 = 0.f, c0 = 1.f, s1 = 0.f, c1 = 1.f;
        if (rope_mode) {
            int hd = gc >> 6;           // head index
            int j0 = gc & 31;           // inv index (even)
            float a0 = (float)hd * __expf(-KLN * (float)j0);
            float a1 = (float)hd * __expf(-KLN * (float)(j0 + 1));
            sincosf(a0, &s0, &c0);
            sincosf(a1, &s1, &c1);
        }
#pragma unroll
        for (int mt = 0; mt < 4; mt++) {
            int gr = m0 + wm * 64 + mt * 16 + (lane >> 2);
#pragma unroll
            for (int half = 0; half < 2; half++) {
                float x0 = acc[mt][nt][half * 2 + 0] + b0;
                float x1 = acc[mt][nt][half * 2 + 1] + b1;
                float y0 = x0, y1 = x1;
                if (rope_mode) {
                    y0 = (x0 * c0 - x1 * s0) * rope_scale;
                    y1 = (x1 * c1 + x0 * s1) * rope_scale;
                }
                *(float2*)&C[(size_t)(gr + half * 8) * EMB + gc] = make_float2(y0, y1);
            }
        }
    }
}

// ---------------------------------------------------------------------------
// Windowed attention, warp-synchronous over keys, packed-f32x2 math.
// Block = (chunk, head, batch), 256 threads = 256 queries; warp w owns
// queries [w*32, w*32+32). All lanes of a warp visit the SAME key y each
// step -> kt/vt smem reads are broadcasts (no bank conflicts).
// Keys processed in batches of 4: interleaved dots (ILP), one rescale per
// batch. All dot/acc FMAs are fma.rn.f32x2 (2 fp32 FMA per instruction).
// ---------------------------------------------------------------------------
__global__ __launch_bounds__(256, 1) void attn_kernel(
    const float* __restrict__ q,
    const float* __restrict__ k,
    const float* __restrict__ v,
    float* __restrict__ ctx)
{
    extern __shared__ float smem[];
    float* kt = smem;                 // [256][64]
    float* vt = smem + 256 * 64;      // [256][64]

    const int c  = blockIdx.x;
    const int hh = blockIdx.y;
    const int bb = blockIdx.z;
    const int tid = threadIdx.x;
    const int w   = tid >> 5;
    const int xq  = tid;                  // query index within chunk
    const int pos = c * WINSZ + xq;

    // q row as 32 packed f32x2 values
    const float* qrow = q + ((size_t)(bb * SEQ + pos)) * EMB + hh * HDIM;
    unsigned long long qp[32];
#pragma unroll
    for (int i = 0; i < 16; i++) {
        ulonglong2 t = *(const ulonglong2*)&qrow[i * 4];
        qp[2 * i] = t.x; qp[2 * i + 1] = t.y;
    }

    unsigned long long ap[32];        // packed accumulator (64 floats)
#pragma unroll
    for (int i = 0; i < 32; i++) ap[i] = 0ull;
    float mval = -1e30f, l = 0.0f;

    // warp-uniform y bounds; lower bounds are ==0 (mod 4), caps are ==3
    // (mod 4), so every non-empty [y0,y1] has length % 4 == 0.
    int wy_lo = w * 32;
    int lob = WINSZ - c * WINSZ;                 // kpos >= 0
    if (wy_lo < lob) wy_lo = lob;
    int wy_hi = w * 32 + 31 + 2 * WINSZ;
    int hib = SEQ - 1 - c * WINSZ + WINSZ;       // kpos <= SEQ-1
    if (hib > 3 * WINSZ - 1) hib = 3 * WINSZ - 1;
    if (wy_hi > hib) wy_hi = hib;

    for (int tile = 0; tile < 3; tile++) {
        const int ybase = tile * 256;
        // cooperative K/V tile load (256 rows x 16 float4)
        for (int i = tid; i < 256 * 16; i += 256) {
            int row = i >> 4;
            int c4  = i & 15;
            int kpos = c * WINSZ + ybase + row - WINSZ;
            float4 kv = make_float4(0.f, 0.f, 0.f, 0.f);
            float4 vv = kv;
            if (kpos >= 0 && kpos < SEQ) {
                size_t off = ((size_t)(bb * SEQ + kpos)) * EMB + hh * HDIM + c4 * 4;
                kv = *(const float4*)&k[off];
                vv = *(const float4*)&v[off];
            }
            *(float4*)&kt[row * 64 + c4 * 4] = kv;
            *(float4*)&vt[row * 64 + c4 * 4] = vv;
        }
        __syncthreads();

        int y0 = wy_lo > ybase ? wy_lo : ybase;
        int y1 = wy_hi < (ybase + 255) ? wy_hi : (ybase + 255);

        for (int y = y0; y <= y1; y += 4) {
            // ---- 4 interleaved packed dot products ----
            float sv[4];
#pragma unroll
            for (int j = 0; j < 4; j++) {
                const ulonglong2* kr = (const ulonglong2*)&kt[(y + j - ybase) * 64];
                unsigned long long d0 = 0ull, d1 = 0ull, d2 = 0ull, d3 = 0ull;
#pragma unroll
                for (int i = 0; i < 8; i++) {
                    ulonglong2 ka = kr[2 * i];
                    ulonglong2 kb = kr[2 * i + 1];
                    FMA_F32X2(d0, qp[4 * i + 0], ka.x, d0);
                    FMA_F32X2(d1, qp[4 * i + 1], ka.y, d1);
                    FMA_F32X2(d2, qp[4 * i + 2], kb.x, d2);
                    FMA_F32X2(d3, qp[4 * i + 3], kb.y, d3);
                }
                ADD_F32X2(d0, d0, d2);
                ADD_F32X2(d1, d1, d3);
                ADD_F32X2(d0, d0, d1);
                float lo, hi;
                UNPACK_F32X2(lo, hi, d0);
                sv[j] = lo + hi;
            }

            // ---- batch max + (rare) rescale ----
            float sm0 = sv[0], sm1 = sv[1], sm2 = sv[2], sm3 = sv[3];
            bool v0 = (unsigned)(y + 0 - xq) <= (unsigned)(2 * WINSZ);
            bool v1b = (unsigned)(y + 1 - xq) <= (unsigned)(2 * WINSZ);
            bool v2 = (unsigned)(y + 2 - xq) <= (unsigned)(2 * WINSZ);
            bool v3 = (unsigned)(y + 3 - xq) <= (unsigned)(2 * WINSZ);
            if (!v0) sm0 = -1e30f;
            if (!v1b) sm1 = -1e30f;
            if (!v2) sm2 = -1e30f;
            if (!v3) sm3 = -1e30f;
            float bm = fmaxf(fmaxf(sm0, sm1), fmaxf(sm2, sm3));
            if (bm > mval) {
                float corr = __expf(mval - bm);
                mval = bm;
                l *= corr;
                unsigned long long cp;
                PACK_F32X2(cp, corr, corr);
#pragma unroll
                for (int i = 0; i < 32; i++) MUL_F32X2(ap[i], ap[i], cp);
            }

            float p0 = v0 ? __expf(sm0 - mval) : 0.0f;
            float p1 = v1b ? __expf(sm1 - mval) : 0.0f;
            float p2 = v2 ? __expf(sm2 - mval) : 0.0f;
            float p3 = v3 ? __expf(sm3 - mval) : 0.0f;
            l += (p0 + p1) + (p2 + p3);

            unsigned long long pp0, pp1, pp2, pp3;
            PACK_F32X2(pp0, p0, p0);
            PACK_F32X2(pp1, p1, p1);
            PACK_F32X2(pp2, p2, p2);
            PACK_F32X2(pp3, p3, p3);

            const ulonglong2* vr0 = (const ulonglong2*)&vt[(y + 0 - ybase) * 64];
            const ulonglong2* vr1 = (const ulonglong2*)&vt[(y + 1 - ybase) * 64];
            const ulonglong2* vr2 = (const ulonglong2*)&vt[(y + 2 - ybase) * 64];
            const ulonglong2* vr3 = (const ulonglong2*)&vt[(y + 3 - ybase) * 64];
#pragma unroll
            for (int i = 0; i < 16; i++) {
                ulonglong2 a0 = vr0[i];
                FMA_F32X2(ap[2 * i], pp0, a0.x, ap[2 * i]);
                FMA_F32X2(ap[2 * i + 1], pp0, a0.y, ap[2 * i + 1]);
                ulonglong2 a1 = vr1[i];
                FMA_F32X2(ap[2 * i], pp1, a1.x, ap[2 * i]);
                FMA_F32X2(ap[2 * i + 1], pp1, a1.y, ap[2 * i + 1]);
                ulonglong2 a2 = vr2[i];
                FMA_F32X2(ap[2 * i], pp2, a2.x, ap[2 * i]);
                FMA_F32X2(ap[2 * i + 1], pp2, a2.y, ap[2 * i + 1]);
                ulonglong2 a3 = vr3[i];
                FMA_F32X2(ap[2 * i], pp3, a3.x, ap[2 * i]);
                FMA_F32X2(ap[2 * i + 1], pp3, a3.y, ap[2 * i + 1]);
            }
        }
        __syncthreads();
    }

    float inv_l = 1.0f / l;
    float* orow = ctx + ((size_t)(bb * SEQ + pos)) * EMB + hh * HDIM;
#pragma unroll
    for (int i = 0; i < 32; i++) {
        float lo, hi;
        UNPACK_F32X2(lo, hi, ap[i]);
        *(float2*)&orow[i * 2] = make_float2(lo * inv_l, hi * inv_l);
    }
}

// ---------------------------------------------------------------------------
extern "C" void kernel_launch(void* const* d_in, const int* in_sizes, int n_in,
                              void* d_out, int out_size)
{
    const float* x  = (const float*)d_in[0];
    const float* Wq = (const float*)d_in[1];
    const float* bq = (const float*)d_in[2];
    const float* Wk = (const float*)d_in[3];
    const float* bk = (const float*)d_in[4];
    const float* Wv = (const float*)d_in[5];
    const float* bv = (const float*)d_in[6];
    const float* Wo = (const float*)d_in[7];
    const float* bo = (const float*)d_in[8];
    float* out = (float*)d_out;

    float *q, *k, *v, *ctx;
    cudaGetSymbolAddress((void**)&q,   g_q);
    cudaGetSymbolAddress((void**)&k,   g_k);
    cudaGetSymbolAddress((void**)&v,   g_v);
    cudaGetSymbolAddress((void**)&ctx, g_ctx);

    const int attn_smem = 2 * 256 * HDIM * (int)sizeof(float);   // 128 KB
    cudaFuncSetAttribute(attn_kernel,
                         cudaFuncAttributeMaxDynamicSharedMemorySize, attn_smem);
    const int gemm_smem = 4 * BUF_BYTES;                          // 73728 B
    cudaFuncSetAttribute(gemm_tf32_kernel,
                         cudaFuncAttributeMaxDynamicSharedMemorySize, gemm_smem);

    dim3 gemm_grid(EMB / BN, M_TOTAL / BM);

    // RoPE fused into Q/K projection epilogues (q also scaled by 1/sqrt(64))
    gemm_tf32_kernel<<<gemm_grid, 256, gemm_smem>>>(x, Wq, bq, q, M_TOTAL, EMB, EMB, 1, 0.125f);
    gemm_tf32_kernel<<<gemm_grid, 256, gemm_smem>>>(x, Wk, bk, k, M_TOTAL, EMB, EMB, 1, 1.0f);
    gemm_tf32_kernel<<<gemm_grid, 256, gemm_smem>>>(x, Wv, bv, v, M_TOTAL, EMB, EMB, 0, 1.0f);

    attn_kernel<<<dim3(NCHUNK, NHEADS, BATCH), 256, attn_smem>>>(q, k, v, ctx);

    gemm_tf32_kernel<<<gemm_grid, 256, gemm_smem>>>(ctx, Wo, bo, out, M_TOTAL, EMB, EMB, 0, 1.0f);
}